// round 16
// baseline (speedup 1.0000x reference)
#include <cuda_runtime.h>
#include <cuda_fp16.h>
#include <cstdint>

// Problem constants
#define BATCH 8192
#define D_IN  1024
#define NH    2048
#define KLR   4
#define NCLS  1000
#define BN_EPS 1e-5f
#define NSEG  256

#define STAGES 3
#define STAGE_BYTES 32768           // A 16KB (128x128B) | B 16KB (128x128B)
#define SMEM_TOTAL (STAGES * STAGE_BYTES)

static __device__ __forceinline__ uint32_t smem_u32(const void* p) {
    uint32_t a;
    asm("{ .reg .u64 t; cvta.to.shared.u64 t, %1; cvt.u32.u64 %0, t; }" : "=r"(a) : "l"(p));
    return a;
}
static __device__ __forceinline__ void cp16(uint32_t dst, const void* src, uint32_t bytes) {
    asm volatile("cp.async.cg.shared.global [%0], [%1], 16, %2;" :: "r"(dst), "l"(src), "r"(bytes) : "memory");
}
#define CP_COMMIT() asm volatile("cp.async.commit_group;" ::: "memory")
#define CP_WAIT(n)  asm volatile("cp.async.wait_group %0;" :: "n"(n) : "memory")
#define LDSM4(r0, r1, r2, r3, a) \
    asm volatile("ldmatrix.sync.aligned.m8n8.x4.shared.b16 {%0,%1,%2,%3}, [%4];" \
        : "=r"(r0), "=r"(r1), "=r"(r2), "=r"(r3) : "r"(a))
#define MMA16816(c, a, b0, b1) \
    asm volatile("mma.sync.aligned.m16n8k16.row.col.f32.f16.f16.f32 " \
        "{%0,%1,%2,%3},{%4,%5,%6,%7},{%8,%9},{%0,%1,%2,%3};" \
        : "+f"((c)[0]), "+f"((c)[1]), "+f"((c)[2]), "+f"((c)[3]) \
        : "r"((a)[0]), "r"((a)[1]), "r"((a)[2]), "r"((a)[3]), "r"(b0), "r"(b1))

// pack 4 floats -> 4 halves (8 bytes)
static __device__ __forceinline__ void store_half4(__half* p, float4 f) {
    __half2* h = (__half2*)p;
    h[0] = __floats2half2_rn(f.x, f.y);
    h[1] = __floats2half2_rn(f.z, f.w);
}

// load fragments for one ks step into buffer `dstbuf`
#define LOADFRAG(dstbuf, baseA, baseB, kc) do { \
    _Pragma("unroll") \
    for (int mi_ = 0; mi_ < 4; mi_++) { \
        int row_ = aRow + mi_ * 16; \
        uint32_t off_ = (uint32_t)(row_ * 128 + ((((kc) + aK8) * 2) ^ ((row_ & 7) << 4))); \
        LDSM4(a[dstbuf][mi_][0], a[dstbuf][mi_][1], a[dstbuf][mi_][2], a[dstbuf][mi_][3], (baseA) + off_); \
    } \
    _Pragma("unroll") \
    for (int nbk_ = 0; nbk_ < 4; nbk_++) { \
        int row_ = bRow + nbk_ * 16; \
        uint32_t off_ = (uint32_t)(row_ * 128 + ((((kc) + bK8) * 2) ^ ((row_ & 7) << 4))); \
        LDSM4(b[dstbuf][nbk_][0], b[dstbuf][nbk_][1], b[dstbuf][nbk_][2], b[dstbuf][nbk_][3], (baseB) + off_); \
    } \
} while (0)

// ---------------- static device scratch ----------------
__device__ float g_S[(size_t)BATCH * NH];
__device__ float g_Pq[(size_t)BATCH * NH];
__device__ float g_t[(size_t)BATCH * NH];
__device__ __align__(1024) __half g_a1x[(size_t)BATCH * D_IN];
__device__ __align__(1024) __half g_a1f[(size_t)BATCH * NH];
__device__ __align__(1024) __half g_b1[(size_t)(NH * KLR + NH) * NH];
__device__ __align__(1024) __half g_b1l[(size_t)NCLS * NH];
__device__ float g_rowsq[BATCH];
__device__ float g_msq[NH];
__device__ float g_c[NH * KLR];
__device__ float g_scale[NH];
__device__ float g_shift[NH];
__device__ float g_psum[NSEG * NH];
__device__ float g_psq[NSEG * NH];

// ===== HMMA fp16 GEMM: 128x128 CTA, 4 warps (2x2), 64x64 warp tile, 2 CTA/SM =====
// Chunk order: wait -> barrier -> LDSM(ks0) -> issue cp.async (fills LDSM shadow) -> MMAs.
__global__ void __launch_bounds__(128, 2)
gemm_mma(const __half* __restrict__ A1, const __half* __restrict__ B1,
         float* __restrict__ Pq, float* __restrict__ Cs, const float* __restrict__ cvec,
         int Mt, int Ncut, int Ntot, int Ns, int NqW, int Kd, const float* __restrict__ bias)
{
    extern __shared__ __align__(1024) char smem[];
    const uint32_t sbase = smem_u32(smem);
    const int tid = threadIdx.x;
    const int wid = tid >> 5;
    const int lane = tid & 31;
    const int wm = wid >> 1;
    const int wn = wid & 1;

    const int nt_total = (Ntot + 127) >> 7;
    const int bw0 = 8;
    const int per_band = Mt * bw0;
    const int band = blockIdx.x / per_band;
    const int rem = blockIdx.x % per_band;
    int nb = nt_total - band * bw0; if (nb > bw0) nb = bw0;
    const int mtile = rem / nb;
    const int ntile = band * bw0 + rem % nb;
    const int row0 = mtile * 128;
    const int col0 = ntile * 128;
    const int nk = Kd >> 6;

    float acc[4][8][4];
#pragma unroll
    for (int i = 0; i < 4; i++)
#pragma unroll
        for (int j = 0; j < 8; j++)
#pragma unroll
            for (int r = 0; r < 4; r++) acc[i][j][r] = 0.f;

    const int aRow = wm * 64 + (lane & 15);
    const int aK8 = (lane >> 4) * 8;
    const int bRow = wn * 64 + (lane & 7) + ((lane >> 4) & 1) * 8;
    const int bK8 = ((lane >> 3) & 1) * 8;

    auto issue = [&](int i) {
        if (i < nk) {
            const int s = i % STAGES;
            const uint32_t stA = sbase + s * STAGE_BYTES;
            const uint32_t stB = stA + 16384;
            const __half* Ab = A1 + (size_t)row0 * Kd + (i << 6);
            const __half* Bb = B1 + (i << 6);
#pragma unroll
            for (int it = 0; it < 8; it++) {
                int id = it * 128 + tid;
                int row = id >> 3, c = id & 7;
                uint32_t off = (uint32_t)(row * 128 + ((c * 16) ^ ((row & 7) << 4)));
                cp16(stA + off, Ab + (size_t)row * Kd + c * 8, 16);
            }
#pragma unroll
            for (int it = 0; it < 8; it++) {
                int id = it * 128 + tid;
                int row = id >> 3, c = id & 7;
                int gn = col0 + row;
                uint32_t bytes = (gn < Ntot) ? 16u : 0u;
                if (gn >= Ntot) gn = col0;
                uint32_t off = (uint32_t)(row * 128 + ((c * 16) ^ ((row & 7) << 4)));
                cp16(stB + off, Bb + (size_t)gn * Kd + c * 8, bytes);
            }
        }
        CP_COMMIT();
    };

#pragma unroll
    for (int i = 0; i < STAGES - 1; i++) issue(i);

    uint32_t a[2][4][4], b[2][4][4];

    for (int i = 0; i < nk; i++) {
        CP_WAIT(STAGES - 2);
        __syncthreads();
        const int s = i % STAGES;
        const uint32_t stA = sbase + s * STAGE_BYTES;
        const uint32_t stB = stA + 16384;

        // ks0 fragments first...
        LOADFRAG(0, stA, stB, 0);
        // ...then issue next-stage cp.asyncs into the LDSM latency shadow.
        // Overwrites stage (i-1): all its readers finished before this chunk's barrier.
        issue(i + STAGES - 1);

#pragma unroll
        for (int ks = 0; ks < 4; ks++) {
            const int cur = ks & 1;
            const int nxt = cur ^ 1;
            if (ks < 3) {
                const int kc = (ks + 1) * 16;
                LOADFRAG(nxt, stA, stB, kc);
            }
#pragma unroll
            for (int mi = 0; mi < 4; mi++)
#pragma unroll
                for (int ni = 0; ni < 8; ni++)
                    MMA16816(acc[mi][ni], a[cur][mi],
                             b[cur][ni >> 1][(ni & 1) * 2], b[cur][ni >> 1][(ni & 1) * 2 + 1]);
        }
    }

    // ---- epilogue ----
#pragma unroll
    for (int mi = 0; mi < 4; mi++) {
        const int m = row0 + wm * 64 + mi * 16 + (lane >> 2);
#pragma unroll
        for (int ni = 0; ni < 8; ni++) {
            const int col = col0 + wn * 64 + ni * 8 + (lane & 3) * 2;
            float2 v0 = make_float2(acc[mi][ni][0], acc[mi][ni][1]);
            float2 v1 = make_float2(acc[mi][ni][2], acc[mi][ni][3]);
            if (col < Ncut) {
                float c0 = cvec[col], c1 = cvec[col + 1];
                float d00 = v0.x - c0, d01 = v0.y - c1;
                float d10 = v1.x - c0, d11 = v1.y - c1;
                float dd0 = d00 * d00 + d01 * d01;
                float dd1 = d10 * d10 + d11 * d11;
                float q0 = dd0 + __shfl_xor_sync(0xffffffffu, dd0, 1);
                float q1 = dd1 + __shfl_xor_sync(0xffffffffu, dd1, 1);
                if ((lane & 1) == 0) {
                    int g = col >> 2;
                    Pq[(size_t)m * NqW + g] = q0;
                    Pq[(size_t)(m + 8) * NqW + g] = q1;
                }
            } else {
                int sc = col - Ncut;
                if (sc < Ns) {
                    if (bias) {
                        float b0 = bias[sc], b1 = bias[sc + 1];
                        v0.x += b0; v0.y += b1; v1.x += b0; v1.y += b1;
                    }
                    *(float2*)(Cs + (size_t)m * Ns + sc) = v0;
                    *(float2*)(Cs + (size_t)(m + 8) * Ns + sc) = v1;
                }
            }
        }
    }
}

// ------- fused cast + rowsq, float4/half2 vectorized -------
__global__ void castx_rowsq(const float* __restrict__ x, __half* __restrict__ xh,
                            float* __restrict__ rsq, int D) {
    int b = blockIdx.x;
    const float* p = x + (size_t)b * D;
    __half* o = xh + (size_t)b * D;
    float s = 0.f;
    for (int i = threadIdx.x * 4; i < D; i += 1024) {
        float4 v = *(const float4*)(p + i);
        store_half4(o + i, v);
        s = fmaf(v.x, v.x, s); s = fmaf(v.y, v.y, s);
        s = fmaf(v.z, v.z, s); s = fmaf(v.w, v.w, s);
    }
    __shared__ float red[256];
    red[threadIdx.x] = s;
    __syncthreads();
    for (int off = 128; off > 0; off >>= 1) {
        if (threadIdx.x < off) red[threadIdx.x] += red[threadIdx.x + off];
        __syncthreads();
    }
    if (threadIdx.x == 0) rsq[b] = red[0];
}

// ---------------- cast: fp32 -> fp16 (vectorized) ----------------
__global__ void castH(const float* __restrict__ src, __half* __restrict__ dst) {
    size_t i = ((size_t)blockIdx.x * 256 + threadIdx.x) * 4;
    float4 v = *(const float4*)(src + i);
    store_half4(dst + i, v);
}

// ------- fused prep + cast (float4 vectorized) -------
__global__ void prep_cast(const float* __restrict__ mu, const float* __restrict__ v,
                          __half* __restrict__ B1,
                          float* __restrict__ msq, float* __restrict__ c, int D) {
    int n = blockIdx.x;
    const float* mp = mu + (size_t)n * D;
    const float* vp = v + (size_t)n * KLR * D;
    __half* bmu = B1 + ((size_t)(NH * KLR) + n) * D;
    __half* bv  = B1 + (size_t)n * KLR * D;
    float acc[5] = {0.f, 0.f, 0.f, 0.f, 0.f};
    for (int i = threadIdx.x * 4; i < D; i += 1024) {
        float4 m = *(const float4*)(mp + i);
        store_half4(bmu + i, m);
        acc[0] = fmaf(m.x, m.x, fmaf(m.y, m.y, fmaf(m.z, m.z, fmaf(m.w, m.w, acc[0]))));
#pragma unroll
        for (int k = 0; k < KLR; k++) {
            float4 vv = *(const float4*)(vp + (size_t)k * D + i);
            store_half4(bv + (size_t)k * D + i, vv);
            acc[k + 1] = fmaf(m.x, vv.x, fmaf(m.y, vv.y, fmaf(m.z, vv.z, fmaf(m.w, vv.w, acc[k + 1]))));
        }
    }
    __shared__ float red[256];
    for (int j = 0; j < 5; j++) {
        red[threadIdx.x] = acc[j];
        __syncthreads();
        for (int off = 128; off > 0; off >>= 1) {
            if (threadIdx.x < off) red[threadIdx.x] += red[threadIdx.x + off];
            __syncthreads();
        }
        if (threadIdx.x == 0) {
            if (j == 0) msq[n] = red[0];
            else        c[n * KLR + (j - 1)] = red[0];
        }
        __syncthreads();
    }
}

// ------- fused quad epilogue + shifted fp32 BN stats, 4 columns per thread -------
__global__ void quad_bnsum(const float* __restrict__ S, const float* __restrict__ Pq,
                           const float* __restrict__ rsq, const float* __restrict__ msq,
                           const float* __restrict__ lam,
                           float* __restrict__ t, float* __restrict__ psum,
                           float* __restrict__ psq, int mode) {
    int n0 = (blockIdx.x * 256 + threadIdx.x) * 4;
    int seg = blockIdx.y;
    const int rows = BATCH / NSEG;   // 32
    float4 lamv = *(const float4*)(lam + n0);
    float4 msqv = *(const float4*)(msq + n0);
    const float shiftv = mode ? 1.0f : 0.0f;
    float sa[4] = {0.f, 0.f, 0.f, 0.f};
    float qa[4] = {0.f, 0.f, 0.f, 0.f};
    size_t b0 = (size_t)seg * rows;
    for (int r = 0; r < rows; r++) {
        size_t b = b0 + r;
        size_t idx = b * NH + n0;
        float rs = rsq[b];
        float4 sv = *(const float4*)(S + idx);
        float4 pv = *(const float4*)(Pq + idx);
        float q0 = lamv.x * (rs - 2.f * sv.x + msqv.x) + pv.x;
        float q1 = lamv.y * (rs - 2.f * sv.y + msqv.y) + pv.y;
        float q2 = lamv.z * (rs - 2.f * sv.z + msqv.z) + pv.z;
        float q3 = lamv.w * (rs - 2.f * sv.w + msqv.w) + pv.w;
        float4 vv;
        if (mode) {
            vv.x = expf(-q0 * (1.0f / (float)NH));
            vv.y = expf(-q1 * (1.0f / (float)NH));
            vv.z = expf(-q2 * (1.0f / (float)NH));
            vv.w = expf(-q3 * (1.0f / (float)NH));
        } else {
            vv.x = -q0; vv.y = -q1; vv.z = -q2; vv.w = -q3;
        }
        *(float4*)(t + idx) = vv;
        float d0 = vv.x - shiftv, d1 = vv.y - shiftv, d2 = vv.z - shiftv, d3 = vv.w - shiftv;
        sa[0] += d0; sa[1] += d1; sa[2] += d2; sa[3] += d3;
        qa[0] = fmaf(d0, d0, qa[0]); qa[1] = fmaf(d1, d1, qa[1]);
        qa[2] = fmaf(d2, d2, qa[2]); qa[3] = fmaf(d3, d3, qa[3]);
    }
    *(float4*)(psum + (size_t)seg * NH + n0) = make_float4(sa[0], sa[1], sa[2], sa[3]);
    *(float4*)(psq + (size_t)seg * NH + n0) = make_float4(qa[0], qa[1], qa[2], qa[3]);
}

// ------- BN finalize: fp64 combine of shifted fp32 partials -------
__global__ void bn_stats(const float* __restrict__ psum, const float* __restrict__ psq,
                         const float* __restrict__ g, const float* __restrict__ be,
                         float* __restrict__ scale, float* __restrict__ shift, int mode) {
    int n = blockIdx.x * 256 + threadIdx.x;
    double s = 0.0, s2 = 0.0;
    for (int i = 0; i < NSEG; i++) { s += (double)psum[i * NH + n]; s2 += (double)psq[i * NH + n]; }
    double md = s * (1.0 / (double)BATCH);
    double var = s2 * (1.0 / (double)BATCH) - md * md;
    double mean = (mode ? 1.0 : 0.0) + md;
    float rstd = (float)(1.0 / sqrt(var + (double)BN_EPS));
    float sc = g[n] * rstd;
    scale[n] = sc;
    shift[n] = be[n] - (float)mean * sc;
}

// ------- BN apply (vectorized) fused with next-layer rowsq -------
__global__ void bn_apply(const float* __restrict__ t, const float* __restrict__ scale,
                         const float* __restrict__ shift,
                         __half* __restrict__ f1, float* __restrict__ rsq,
                         float* o1, float* o2, int relu) {
    int b = blockIdx.x;
    const float* tp = t + (size_t)b * NH;
    __half* fp = f1 + (size_t)b * NH;
    float s = 0.f;
    for (int n = threadIdx.x * 4; n < NH; n += 1024) {
        float4 tv = *(const float4*)(tp + n);
        float4 sc = *(const float4*)(scale + n);
        float4 sh = *(const float4*)(shift + n);
        float4 vv;
        vv.x = fmaf(tv.x, sc.x, sh.x);
        vv.y = fmaf(tv.y, sc.y, sh.y);
        vv.z = fmaf(tv.z, sc.z, sh.z);
        vv.w = fmaf(tv.w, sc.w, sh.w);
        if (relu) {
            vv.x = fmaxf(vv.x, 0.f); vv.y = fmaxf(vv.y, 0.f);
            vv.z = fmaxf(vv.z, 0.f); vv.w = fmaxf(vv.w, 0.f);
        }
        store_half4(fp + n, vv);
        s = fmaf(vv.x, vv.x, s); s = fmaf(vv.y, vv.y, s);
        s = fmaf(vv.z, vv.z, s); s = fmaf(vv.w, vv.w, s);
        if (o1) *(float4*)(o1 + (size_t)b * NH + n) = vv;
        if (o2) *(float4*)(o2 + (size_t)b * NH + n) = vv;
    }
    if (rsq) {
        __shared__ float red[256];
        red[threadIdx.x] = s;
        __syncthreads();
        for (int off = 128; off > 0; off >>= 1) {
            if (threadIdx.x < off) red[threadIdx.x] += red[threadIdx.x + off];
            __syncthreads();
        }
        if (threadIdx.x == 0) rsq[b] = red[0];
    }
}

// ---------------- host orchestration ----------------
extern "C" void kernel_launch(void* const* d_in, const int* in_sizes, int n_in,
                              void* d_out, int out_size) {
    const float* x    = (const float*)d_in[0];
    const float* mu1  = (const float*)d_in[1];
    const float* lam1 = (const float*)d_in[2];
    const float* v1   = (const float*)d_in[3];
    const float* g1   = (const float*)d_in[4];
    const float* b1   = (const float*)d_in[5];
    const float* mu2  = (const float*)d_in[6];
    const float* lam2 = (const float*)d_in[7];
    const float* v2   = (const float*)d_in[8];
    const float* g2   = (const float*)d_in[9];
    const float* b2   = (const float*)d_in[10];
    const float* Wl   = (const float*)d_in[11];
    const float* bl   = (const float*)d_in[12];

    float *pS, *pPq, *pT, *pR, *pM, *pC, *pScale, *pShift, *pPsum, *pPsq;
    __half *pA1x, *pA1f, *pB1, *pB1l;
    cudaGetSymbolAddress((void**)&pS, g_S);
    cudaGetSymbolAddress((void**)&pPq, g_Pq);
    cudaGetSymbolAddress((void**)&pT, g_t);
    cudaGetSymbolAddress((void**)&pA1x, g_a1x);
    cudaGetSymbolAddress((void**)&pA1f, g_a1f);
    cudaGetSymbolAddress((void**)&pB1, g_b1);
    cudaGetSymbolAddress((void**)&pB1l, g_b1l);
    cudaGetSymbolAddress((void**)&pR, g_rowsq);
    cudaGetSymbolAddress((void**)&pM, g_msq);
    cudaGetSymbolAddress((void**)&pC, g_c);
    cudaGetSymbolAddress((void**)&pScale, g_scale);
    cudaGetSymbolAddress((void**)&pShift, g_shift);
    cudaGetSymbolAddress((void**)&pPsum, g_psum);
    cudaGetSymbolAddress((void**)&pPsq, g_psq);

    cudaFuncSetAttribute(gemm_mma, cudaFuncAttributeMaxDynamicSharedMemorySize, SMEM_TOTAL);

    const size_t LOGITS_SZ = (size_t)BATCH * NCLS;
    const size_t FEAT_SZ   = (size_t)BATCH * NH;
    float* out = (float*)d_out;
    size_t extra = ((size_t)out_size > LOGITS_SZ) ? ((size_t)out_size - LOGITS_SZ) / FEAT_SZ : 0;
    float* f1dst = (extra >= 1) ? out + LOGITS_SZ : nullptr;
    float* f2a   = (extra >= 2) ? out + LOGITS_SZ + FEAT_SZ : nullptr;
    float* f2b   = (extra >= 3) ? out + LOGITS_SZ + 2 * FEAT_SZ : nullptr;

    dim3 bn_grid(NH / 1024, NSEG);       // (2, 256)
    const int Mt = BATCH / 128;
    const int NMERGED = NH * (KLR + 1);
    const int merged_grid = Mt * (NMERGED / 128);

    // ---------- Layer 1 ----------
    castx_rowsq<<<BATCH, 256>>>(x, pA1x, pR, D_IN);
    prep_cast<<<NH, 256>>>(mu1, v1, pB1, pM, pC, D_IN);
    gemm_mma<<<merged_grid, 128, SMEM_TOTAL>>>(pA1x, pB1, pPq, pS, pC, Mt, NH * KLR, NMERGED, NH, NH, D_IN, nullptr);
    quad_bnsum<<<bn_grid, 256>>>(pS, pPq, pR, pM, lam1, pT, pPsum, pPsq, 0);
    bn_stats<<<NH / 256, 256>>>(pPsum, pPsq, g1, b1, pScale, pShift, 0);
    bn_apply<<<BATCH, 256>>>(pT, pScale, pShift, pA1f, pR, f1dst, nullptr, 0);

    // ---------- Layer 2 ----------
    prep_cast<<<NH, 256>>>(mu2, v2, pB1, pM, pC, NH);
    gemm_mma<<<merged_grid, 128, SMEM_TOTAL>>>(pA1f, pB1, pPq, pS, pC, Mt, NH * KLR, NMERGED, NH, NH, NH, nullptr);
    quad_bnsum<<<bn_grid, 256>>>(pS, pPq, pR, pM, lam2, pT, pPsum, pPsq, 1);
    bn_stats<<<NH / 256, 256>>>(pPsum, pPsq, g2, b2, pScale, pShift, 1);
    bn_apply<<<BATCH, 256>>>(pT, pScale, pShift, pA1f, nullptr, f2a, f2b, 1);

    // ---------- Logits ----------
    castH<<<(NCLS * NH) / 1024, 256>>>(Wl, pB1l);
    gemm_mma<<<Mt * ((NCLS + 127) / 128), 128, SMEM_TOTAL>>>(pA1f, pB1l, nullptr, out, nullptr, Mt, 0, NCLS, NCLS, 0, NH, bl);
}

// round 17
// speedup vs baseline: 1.0441x; 1.0441x over previous
#include <cuda_runtime.h>
#include <cuda_fp16.h>
#include <cstdint>

// Problem constants
#define BATCH 8192
#define D_IN  1024
#define NH    2048
#define KLR   4
#define NCLS  1000
#define BN_EPS 1e-5f
#define NSEG  256

#define STAGES 3
#define STAGE_BYTES 32768           // A 16KB (128x128B) | B 16KB (128x128B)
#define SMEM_TOTAL (STAGES * STAGE_BYTES)

static __device__ __forceinline__ uint32_t smem_u32(const void* p) {
    uint32_t a;
    asm("{ .reg .u64 t; cvta.to.shared.u64 t, %1; cvt.u32.u64 %0, t; }" : "=r"(a) : "l"(p));
    return a;
}
static __device__ __forceinline__ void cp16(uint32_t dst, const void* src, uint32_t bytes) {
    asm volatile("cp.async.cg.shared.global [%0], [%1], 16, %2;" :: "r"(dst), "l"(src), "r"(bytes) : "memory");
}
#define CP_COMMIT() asm volatile("cp.async.commit_group;" ::: "memory")
#define CP_WAIT(n)  asm volatile("cp.async.wait_group %0;" :: "n"(n) : "memory")
#define LDSM4(r0, r1, r2, r3, a) \
    asm volatile("ldmatrix.sync.aligned.m8n8.x4.shared.b16 {%0,%1,%2,%3}, [%4];" \
        : "=r"(r0), "=r"(r1), "=r"(r2), "=r"(r3) : "r"(a))
#define MMA16816(c, a, b0, b1) \
    asm volatile("mma.sync.aligned.m16n8k16.row.col.f32.f16.f16.f32 " \
        "{%0,%1,%2,%3},{%4,%5,%6,%7},{%8,%9},{%0,%1,%2,%3};" \
        : "+f"((c)[0]), "+f"((c)[1]), "+f"((c)[2]), "+f"((c)[3]) \
        : "r"((a)[0]), "r"((a)[1]), "r"((a)[2]), "r"((a)[3]), "r"(b0), "r"(b1))

// pack 4 floats -> 4 halves (8 bytes)
static __device__ __forceinline__ void store_half4(__half* p, float4 f) {
    __half2* h = (__half2*)p;
    h[0] = __floats2half2_rn(f.x, f.y);
    h[1] = __floats2half2_rn(f.z, f.w);
}

// load fragments for one ks step into buffer `dstbuf`
#define LOADFRAG(dstbuf, baseA, baseB, kc) do { \
    _Pragma("unroll") \
    for (int mi_ = 0; mi_ < 4; mi_++) { \
        int row_ = aRow + mi_ * 16; \
        uint32_t off_ = (uint32_t)(row_ * 128 + ((((kc) + aK8) * 2) ^ ((row_ & 7) << 4))); \
        LDSM4(a[dstbuf][mi_][0], a[dstbuf][mi_][1], a[dstbuf][mi_][2], a[dstbuf][mi_][3], (baseA) + off_); \
    } \
    _Pragma("unroll") \
    for (int nbk_ = 0; nbk_ < 4; nbk_++) { \
        int row_ = bRow + nbk_ * 16; \
        uint32_t off_ = (uint32_t)(row_ * 128 + ((((kc) + bK8) * 2) ^ ((row_ & 7) << 4))); \
        LDSM4(b[dstbuf][nbk_][0], b[dstbuf][nbk_][1], b[dstbuf][nbk_][2], b[dstbuf][nbk_][3], (baseB) + off_); \
    } \
} while (0)

// ---------------- static device scratch ----------------
__device__ float g_S[(size_t)BATCH * NH];
__device__ float g_Pq[(size_t)BATCH * NH];
__device__ float g_t[(size_t)BATCH * NH];
__device__ __align__(1024) __half g_a1x[(size_t)BATCH * D_IN];
__device__ __align__(1024) __half g_a1f[(size_t)BATCH * NH];
__device__ __align__(1024) __half g_b1[(size_t)(NH * KLR + NH) * NH];
__device__ __align__(1024) __half g_b1l[(size_t)NCLS * NH];
__device__ float g_rowsq[BATCH];
__device__ float g_msq[NH];
__device__ float g_c[NH * KLR];
__device__ float g_scale[NH];
__device__ float g_shift[NH];
__device__ float g_psum[NSEG * NH];
__device__ float g_psq[NSEG * NH];

// ===== HMMA fp16 GEMM: 128x128 CTA, 4 warps (2x2), 64x64 warp tile, 2 CTA/SM =====
// R12 chunk schedule (issue at loop end) + hoisted cp.async addressing.
__global__ void __launch_bounds__(128, 2)
gemm_mma(const __half* __restrict__ A1, const __half* __restrict__ B1,
         float* __restrict__ Pq, float* __restrict__ Cs, const float* __restrict__ cvec,
         int Mt, int Ncut, int Ntot, int Ns, int NqW, int Kd, const float* __restrict__ bias)
{
    extern __shared__ __align__(1024) char smem[];
    const uint32_t sbase = smem_u32(smem);
    const int tid = threadIdx.x;
    const int wid = tid >> 5;
    const int lane = tid & 31;
    const int wm = wid >> 1;
    const int wn = wid & 1;

    const int nt_total = (Ntot + 127) >> 7;
    const int bw0 = 8;
    const int per_band = Mt * bw0;
    const int band = blockIdx.x / per_band;
    const int rem = blockIdx.x % per_band;
    int nb = nt_total - band * bw0; if (nb > bw0) nb = bw0;
    const int mtile = rem / nb;
    const int ntile = band * bw0 + rem % nb;
    const int row0 = mtile * 128;
    const int col0 = ntile * 128;
    const int nk = Kd >> 6;

    // ---- hoisted cp.async addressing (loop-invariant per thread) ----
    uint32_t offs[8];     // swizzled smem offsets (same pattern for A and B)
    uint32_t srcA[8];     // element offsets row*Kd + c*8 (A rows)
    uint32_t srcB[8];     // element offsets gn*Kd + c*8 (B rows, clamped)
    uint32_t bbytes[8];   // 16 or 0 per B transfer
#pragma unroll
    for (int it = 0; it < 8; it++) {
        int id = it * 128 + tid;
        int row = id >> 3, c = id & 7;
        offs[it] = (uint32_t)(row * 128 + ((c * 16) ^ ((row & 7) << 4)));
        srcA[it] = (uint32_t)(row * Kd + c * 8);
        int gn = col0 + row;
        bbytes[it] = (gn < Ntot) ? 16u : 0u;
        if (gn >= Ntot) gn = col0;
        srcB[it] = (uint32_t)(gn * Kd + c * 8);
    }
    const __half* Arow0 = A1 + (size_t)row0 * Kd;

    float acc[4][8][4];
#pragma unroll
    for (int i = 0; i < 4; i++)
#pragma unroll
        for (int j = 0; j < 8; j++)
#pragma unroll
            for (int r = 0; r < 4; r++) acc[i][j][r] = 0.f;

    const int aRow = wm * 64 + (lane & 15);
    const int aK8 = (lane >> 4) * 8;
    const int bRow = wn * 64 + (lane & 7) + ((lane >> 4) & 1) * 8;
    const int bK8 = ((lane >> 3) & 1) * 8;

    auto issue = [&](int i) {
        if (i < nk) {
            const int s = i % STAGES;
            const uint32_t stA = sbase + s * STAGE_BYTES;
            const uint32_t stB = stA + 16384;
            const __half* Ab = Arow0 + (i << 6);
            const __half* Bb = B1 + (i << 6);
#pragma unroll
            for (int it = 0; it < 8; it++)
                cp16(stA + offs[it], Ab + srcA[it], 16);
#pragma unroll
            for (int it = 0; it < 8; it++)
                cp16(stB + offs[it], Bb + srcB[it], bbytes[it]);
        }
        CP_COMMIT();
    };

#pragma unroll
    for (int i = 0; i < STAGES - 1; i++) issue(i);

    uint32_t a[2][4][4], b[2][4][4];

    for (int i = 0; i < nk; i++) {
        CP_WAIT(STAGES - 2);
        __syncthreads();
        const int s = i % STAGES;
        const uint32_t stA = sbase + s * STAGE_BYTES;
        const uint32_t stB = stA + 16384;

        LOADFRAG(0, stA, stB, 0);

#pragma unroll
        for (int ks = 0; ks < 4; ks++) {
            const int cur = ks & 1;
            const int nxt = cur ^ 1;
            if (ks < 3) {
                const int kc = (ks + 1) * 16;
                LOADFRAG(nxt, stA, stB, kc);
            }
#pragma unroll
            for (int mi = 0; mi < 4; mi++)
#pragma unroll
                for (int ni = 0; ni < 8; ni++)
                    MMA16816(acc[mi][ni], a[cur][mi],
                             b[cur][ni >> 1][(ni & 1) * 2], b[cur][ni >> 1][(ni & 1) * 2 + 1]);
        }
        issue(i + STAGES - 1);
    }

    // ---- epilogue ----
#pragma unroll
    for (int mi = 0; mi < 4; mi++) {
        const int m = row0 + wm * 64 + mi * 16 + (lane >> 2);
#pragma unroll
        for (int ni = 0; ni < 8; ni++) {
            const int col = col0 + wn * 64 + ni * 8 + (lane & 3) * 2;
            float2 v0 = make_float2(acc[mi][ni][0], acc[mi][ni][1]);
            float2 v1 = make_float2(acc[mi][ni][2], acc[mi][ni][3]);
            if (col < Ncut) {
                float c0 = cvec[col], c1 = cvec[col + 1];
                float d00 = v0.x - c0, d01 = v0.y - c1;
                float d10 = v1.x - c0, d11 = v1.y - c1;
                float dd0 = d00 * d00 + d01 * d01;
                float dd1 = d10 * d10 + d11 * d11;
                float q0 = dd0 + __shfl_xor_sync(0xffffffffu, dd0, 1);
                float q1 = dd1 + __shfl_xor_sync(0xffffffffu, dd1, 1);
                if ((lane & 1) == 0) {
                    int g = col >> 2;
                    Pq[(size_t)m * NqW + g] = q0;
                    Pq[(size_t)(m + 8) * NqW + g] = q1;
                }
            } else {
                int sc = col - Ncut;
                if (sc < Ns) {
                    if (bias) {
                        float b0 = bias[sc], b1 = bias[sc + 1];
                        v0.x += b0; v0.y += b1; v1.x += b0; v1.y += b1;
                    }
                    *(float2*)(Cs + (size_t)m * Ns + sc) = v0;
                    *(float2*)(Cs + (size_t)(m + 8) * Ns + sc) = v1;
                }
            }
        }
    }
}

// ------- fused cast + rowsq, float4/half2 vectorized -------
__global__ void castx_rowsq(const float* __restrict__ x, __half* __restrict__ xh,
                            float* __restrict__ rsq, int D) {
    int b = blockIdx.x;
    const float* p = x + (size_t)b * D;
    __half* o = xh + (size_t)b * D;
    float s = 0.f;
    for (int i = threadIdx.x * 4; i < D; i += 1024) {
        float4 v = *(const float4*)(p + i);
        store_half4(o + i, v);
        s = fmaf(v.x, v.x, s); s = fmaf(v.y, v.y, s);
        s = fmaf(v.z, v.z, s); s = fmaf(v.w, v.w, s);
    }
    __shared__ float red[256];
    red[threadIdx.x] = s;
    __syncthreads();
    for (int off = 128; off > 0; off >>= 1) {
        if (threadIdx.x < off) red[threadIdx.x] += red[threadIdx.x + off];
        __syncthreads();
    }
    if (threadIdx.x == 0) rsq[b] = red[0];
}

// ---------------- cast: fp32 -> fp16 (vectorized) ----------------
__global__ void castH(const float* __restrict__ src, __half* __restrict__ dst) {
    size_t i = ((size_t)blockIdx.x * 256 + threadIdx.x) * 4;
    float4 v = *(const float4*)(src + i);
    store_half4(dst + i, v);
}

// ------- fused prep + cast (float4 vectorized) -------
__global__ void prep_cast(const float* __restrict__ mu, const float* __restrict__ v,
                          __half* __restrict__ B1,
                          float* __restrict__ msq, float* __restrict__ c, int D) {
    int n = blockIdx.x;
    const float* mp = mu + (size_t)n * D;
    const float* vp = v + (size_t)n * KLR * D;
    __half* bmu = B1 + ((size_t)(NH * KLR) + n) * D;
    __half* bv  = B1 + (size_t)n * KLR * D;
    float acc[5] = {0.f, 0.f, 0.f, 0.f, 0.f};
    for (int i = threadIdx.x * 4; i < D; i += 1024) {
        float4 m = *(const float4*)(mp + i);
        store_half4(bmu + i, m);
        acc[0] = fmaf(m.x, m.x, fmaf(m.y, m.y, fmaf(m.z, m.z, fmaf(m.w, m.w, acc[0]))));
#pragma unroll
        for (int k = 0; k < KLR; k++) {
            float4 vv = *(const float4*)(vp + (size_t)k * D + i);
            store_half4(bv + (size_t)k * D + i, vv);
            acc[k + 1] = fmaf(m.x, vv.x, fmaf(m.y, vv.y, fmaf(m.z, vv.z, fmaf(m.w, vv.w, acc[k + 1]))));
        }
    }
    __shared__ float red[256];
    for (int j = 0; j < 5; j++) {
        red[threadIdx.x] = acc[j];
        __syncthreads();
        for (int off = 128; off > 0; off >>= 1) {
            if (threadIdx.x < off) red[threadIdx.x] += red[threadIdx.x + off];
            __syncthreads();
        }
        if (threadIdx.x == 0) {
            if (j == 0) msq[n] = red[0];
            else        c[n * KLR + (j - 1)] = red[0];
        }
        __syncthreads();
    }
}

// ------- fused quad epilogue + shifted fp32 BN stats, 4 columns per thread -------
__global__ void quad_bnsum(const float* __restrict__ S, const float* __restrict__ Pq,
                           const float* __restrict__ rsq, const float* __restrict__ msq,
                           const float* __restrict__ lam,
                           float* __restrict__ t, float* __restrict__ psum,
                           float* __restrict__ psq, int mode) {
    int n0 = (blockIdx.x * 256 + threadIdx.x) * 4;
    int seg = blockIdx.y;
    const int rows = BATCH / NSEG;   // 32
    float4 lamv = *(const float4*)(lam + n0);
    float4 msqv = *(const float4*)(msq + n0);
    const float shiftv = mode ? 1.0f : 0.0f;
    float sa[4] = {0.f, 0.f, 0.f, 0.f};
    float qa[4] = {0.f, 0.f, 0.f, 0.f};
    size_t b0 = (size_t)seg * rows;
    for (int r = 0; r < rows; r++) {
        size_t b = b0 + r;
        size_t idx = b * NH + n0;
        float rs = rsq[b];
        float4 sv = *(const float4*)(S + idx);
        float4 pv = *(const float4*)(Pq + idx);
        float q0 = lamv.x * (rs - 2.f * sv.x + msqv.x) + pv.x;
        float q1 = lamv.y * (rs - 2.f * sv.y + msqv.y) + pv.y;
        float q2 = lamv.z * (rs - 2.f * sv.z + msqv.z) + pv.z;
        float q3 = lamv.w * (rs - 2.f * sv.w + msqv.w) + pv.w;
        float4 vv;
        if (mode) {
            vv.x = expf(-q0 * (1.0f / (float)NH));
            vv.y = expf(-q1 * (1.0f / (float)NH));
            vv.z = expf(-q2 * (1.0f / (float)NH));
            vv.w = expf(-q3 * (1.0f / (float)NH));
        } else {
            vv.x = -q0; vv.y = -q1; vv.z = -q2; vv.w = -q3;
        }
        *(float4*)(t + idx) = vv;
        float d0 = vv.x - shiftv, d1 = vv.y - shiftv, d2 = vv.z - shiftv, d3 = vv.w - shiftv;
        sa[0] += d0; sa[1] += d1; sa[2] += d2; sa[3] += d3;
        qa[0] = fmaf(d0, d0, qa[0]); qa[1] = fmaf(d1, d1, qa[1]);
        qa[2] = fmaf(d2, d2, qa[2]); qa[3] = fmaf(d3, d3, qa[3]);
    }
    *(float4*)(psum + (size_t)seg * NH + n0) = make_float4(sa[0], sa[1], sa[2], sa[3]);
    *(float4*)(psq + (size_t)seg * NH + n0) = make_float4(qa[0], qa[1], qa[2], qa[3]);
}

// ------- BN finalize: fp64 combine of shifted fp32 partials -------
__global__ void bn_stats(const float* __restrict__ psum, const float* __restrict__ psq,
                         const float* __restrict__ g, const float* __restrict__ be,
                         float* __restrict__ scale, float* __restrict__ shift, int mode) {
    int n = blockIdx.x * 256 + threadIdx.x;
    double s = 0.0, s2 = 0.0;
    for (int i = 0; i < NSEG; i++) { s += (double)psum[i * NH + n]; s2 += (double)psq[i * NH + n]; }
    double md = s * (1.0 / (double)BATCH);
    double var = s2 * (1.0 / (double)BATCH) - md * md;
    double mean = (mode ? 1.0 : 0.0) + md;
    float rstd = (float)(1.0 / sqrt(var + (double)BN_EPS));
    float sc = g[n] * rstd;
    scale[n] = sc;
    shift[n] = be[n] - (float)mean * sc;
}

// ------- BN apply (vectorized) fused with next-layer rowsq -------
__global__ void bn_apply(const float* __restrict__ t, const float* __restrict__ scale,
                         const float* __restrict__ shift,
                         __half* __restrict__ f1, float* __restrict__ rsq,
                         float* o1, float* o2, int relu) {
    int b = blockIdx.x;
    const float* tp = t + (size_t)b * NH;
    __half* fp = f1 + (size_t)b * NH;
    float s = 0.f;
    for (int n = threadIdx.x * 4; n < NH; n += 1024) {
        float4 tv = *(const float4*)(tp + n);
        float4 sc = *(const float4*)(scale + n);
        float4 sh = *(const float4*)(shift + n);
        float4 vv;
        vv.x = fmaf(tv.x, sc.x, sh.x);
        vv.y = fmaf(tv.y, sc.y, sh.y);
        vv.z = fmaf(tv.z, sc.z, sh.z);
        vv.w = fmaf(tv.w, sc.w, sh.w);
        if (relu) {
            vv.x = fmaxf(vv.x, 0.f); vv.y = fmaxf(vv.y, 0.f);
            vv.z = fmaxf(vv.z, 0.f); vv.w = fmaxf(vv.w, 0.f);
        }
        store_half4(fp + n, vv);
        s = fmaf(vv.x, vv.x, s); s = fmaf(vv.y, vv.y, s);
        s = fmaf(vv.z, vv.z, s); s = fmaf(vv.w, vv.w, s);
        if (o1) *(float4*)(o1 + (size_t)b * NH + n) = vv;
        if (o2) *(float4*)(o2 + (size_t)b * NH + n) = vv;
    }
    if (rsq) {
        __shared__ float red[256];
        red[threadIdx.x] = s;
        __syncthreads();
        for (int off = 128; off > 0; off >>= 1) {
            if (threadIdx.x < off) red[threadIdx.x] += red[threadIdx.x + off];
            __syncthreads();
        }
        if (threadIdx.x == 0) rsq[b] = red[0];
    }
}

// ---------------- host orchestration ----------------
extern "C" void kernel_launch(void* const* d_in, const int* in_sizes, int n_in,
                              void* d_out, int out_size) {
    const float* x    = (const float*)d_in[0];
    const float* mu1  = (const float*)d_in[1];
    const float* lam1 = (const float*)d_in[2];
    const float* v1   = (const float*)d_in[3];
    const float* g1   = (const float*)d_in[4];
    const float* b1   = (const float*)d_in[5];
    const float* mu2  = (const float*)d_in[6];
    const float* lam2 = (const float*)d_in[7];
    const float* v2   = (const float*)d_in[8];
    const float* g2   = (const float*)d_in[9];
    const float* b2   = (const float*)d_in[10];
    const float* Wl   = (const float*)d_in[11];
    const float* bl   = (const float*)d_in[12];

    float *pS, *pPq, *pT, *pR, *pM, *pC, *pScale, *pShift, *pPsum, *pPsq;
    __half *pA1x, *pA1f, *pB1, *pB1l;
    cudaGetSymbolAddress((void**)&pS, g_S);
    cudaGetSymbolAddress((void**)&pPq, g_Pq);
    cudaGetSymbolAddress((void**)&pT, g_t);
    cudaGetSymbolAddress((void**)&pA1x, g_a1x);
    cudaGetSymbolAddress((void**)&pA1f, g_a1f);
    cudaGetSymbolAddress((void**)&pB1, g_b1);
    cudaGetSymbolAddress((void**)&pB1l, g_b1l);
    cudaGetSymbolAddress((void**)&pR, g_rowsq);
    cudaGetSymbolAddress((void**)&pM, g_msq);
    cudaGetSymbolAddress((void**)&pC, g_c);
    cudaGetSymbolAddress((void**)&pScale, g_scale);
    cudaGetSymbolAddress((void**)&pShift, g_shift);
    cudaGetSymbolAddress((void**)&pPsum, g_psum);
    cudaGetSymbolAddress((void**)&pPsq, g_psq);

    cudaFuncSetAttribute(gemm_mma, cudaFuncAttributeMaxDynamicSharedMemorySize, SMEM_TOTAL);

    const size_t LOGITS_SZ = (size_t)BATCH * NCLS;
    const size_t FEAT_SZ   = (size_t)BATCH * NH;
    float* out = (float*)d_out;
    size_t extra = ((size_t)out_size > LOGITS_SZ) ? ((size_t)out_size - LOGITS_SZ) / FEAT_SZ : 0;
    float* f1dst = (extra >= 1) ? out + LOGITS_SZ : nullptr;
    float* f2a   = (extra >= 2) ? out + LOGITS_SZ + FEAT_SZ : nullptr;
    float* f2b   = (extra >= 3) ? out + LOGITS_SZ + 2 * FEAT_SZ : nullptr;

    dim3 bn_grid(NH / 1024, NSEG);       // (2, 256)
    const int Mt = BATCH / 128;
    const int NMERGED = NH * (KLR + 1);
    const int merged_grid = Mt * (NMERGED / 128);

    // ---------- Layer 1 ----------
    castx_rowsq<<<BATCH, 256>>>(x, pA1x, pR, D_IN);
    prep_cast<<<NH, 256>>>(mu1, v1, pB1, pM, pC, D_IN);
    gemm_mma<<<merged_grid, 128, SMEM_TOTAL>>>(pA1x, pB1, pPq, pS, pC, Mt, NH * KLR, NMERGED, NH, NH, D_IN, nullptr);
    quad_bnsum<<<bn_grid, 256>>>(pS, pPq, pR, pM, lam1, pT, pPsum, pPsq, 0);
    bn_stats<<<NH / 256, 256>>>(pPsum, pPsq, g1, b1, pScale, pShift, 0);
    bn_apply<<<BATCH, 256>>>(pT, pScale, pShift, pA1f, pR, f1dst, nullptr, 0);

    // ---------- Layer 2 ----------
    prep_cast<<<NH, 256>>>(mu2, v2, pB1, pM, pC, NH);
    gemm_mma<<<merged_grid, 128, SMEM_TOTAL>>>(pA1f, pB1, pPq, pS, pC, Mt, NH * KLR, NMERGED, NH, NH, NH, nullptr);
    quad_bnsum<<<bn_grid, 256>>>(pS, pPq, pR, pM, lam2, pT, pPsum, pPsq, 1);
    bn_stats<<<NH / 256, 256>>>(pPsum, pPsq, g2, b2, pScale, pShift, 1);
    bn_apply<<<BATCH, 256>>>(pT, pScale, pShift, pA1f, nullptr, f2a, f2b, 1);

    // ---------- Logits ----------
    castH<<<(NCLS * NH) / 1024, 256>>>(Wl, pB1l);
    gemm_mma<<<Mt * ((NCLS + 127) / 128), 128, SMEM_TOTAL>>>(pA1f, pB1l, nullptr, out, nullptr, Mt, 0, NCLS, NCLS, 0, NH, bl);
}